// round 13
// baseline (speedup 1.0000x reference)
#include <cuda_runtime.h>
#include <cuda_bf16.h>
#include <math.h>
#include <stdint.h>

#define N_TABLES 26
#define ROWS_T   100001
#define EDIM     64
#define BATCH    8192
#define POOL_L   4
#define NFEAT    (N_TABLES + 1)            // 27
#define NPAIRS   (NFEAT * (NFEAT - 1) / 2) // 351
#define RDIM     (EDIM + NPAIRS)           // 415
#define RLD      416                       // padded row stride for R
#define FEAT_LD  (NFEAT * EDIM)            // 1728

// ---------------- scratch (device globals; no allocation allowed) ----------
__device__ float g_x1[BATCH * 512];
__device__ float g_x2[BATCH * 256];
__device__ float g_feat[BATCH * FEAT_LD];
__device__ float g_R[BATCH * RLD];
__device__ float g_z1[BATCH * 512];
__device__ float g_w0p[512 * RLD];          // top_w0 padded + tf32-rounded
__device__ float g_w1c[256 * 512];          // bot_w1 tf32-rounded
__device__ float g_w2c[64 * 256];           // bot_w2 tf32-rounded
__device__ float g_wt1c[256 * 512];         // top_w1 tf32-rounded

// ---------------- tf32 helpers ---------------------------------------------
__device__ __forceinline__ uint32_t f2tf(float f) {
    uint32_t u;
    asm("cvt.rna.tf32.f32 %0, %1;" : "=r"(u) : "f"(f));
    return u;
}
__device__ __forceinline__ float f2tff(float f) { return __uint_as_float(f2tf(f)); }

__device__ __forceinline__ void mma_tf32(float* c, const uint32_t* a, const uint32_t* b) {
    asm volatile(
        "mma.sync.aligned.m16n8k8.row.col.f32.tf32.tf32.f32 "
        "{%0,%1,%2,%3}, {%4,%5,%6,%7}, {%8,%9}, {%0,%1,%2,%3};"
        : "+f"(c[0]), "+f"(c[1]), "+f"(c[2]), "+f"(c[3])
        : "r"(a[0]), "r"(a[1]), "r"(a[2]), "r"(a[3]), "r"(b[0]), "r"(b[1]));
}

__device__ __forceinline__ void cp16(void* smem_dst, const void* gsrc) {
    uint32_t s = (uint32_t)__cvta_generic_to_shared(smem_dst);
    asm volatile("cp.async.cg.shared.global [%0], [%1], 16;" :: "r"(s), "l"(gsrc));
}
#define CP_COMMIT()  asm volatile("cp.async.commit_group;")
#define CP_WAIT(n)   asm volatile("cp.async.wait_group %0;" :: "n"(n))

// ============================================================================
// TF32 GEMM 128x128, cp.async double-buffered (PROVEN R11 mainloop).
// Inputs must be tf32-rounded. C = relu(A @ W^T + bias).
// ============================================================================
#define GTM 128
#define GTN 128
#define GBK 16
#define SLD 20

__global__ __launch_bounds__(256)
void gemm_tf32(const float* __restrict__ A, int lda,
               const float* __restrict__ W, int ldw,
               const float* __restrict__ bias,
               float* __restrict__ C, int ldc,
               int K, int round_out)
{
    __shared__ uint32_t sA[2][GTM * SLD];
    __shared__ uint32_t sB[2][GTN * SLD];

    const int tid  = threadIdx.x;
    const int bm   = blockIdx.y * GTM;
    const int bn   = blockIdx.x * GTN;
    const int wid  = tid >> 5;
    const int lane = tid & 31;
    const int wm   = (wid >> 2) * 64;
    const int wn   = (wid & 3) * 32;
    const int lr   = lane >> 2;
    const int lc   = lane & 3;

    float acc[4][4][4];
    #pragma unroll
    for (int i = 0; i < 4; i++)
        #pragma unroll
        for (int j = 0; j < 4; j++)
            #pragma unroll
            for (int k = 0; k < 4; k++) acc[i][j][k] = 0.f;

    auto issue_tile = [&](int k0, int buf) {
        #pragma unroll
        for (int j = 0; j < 2; j++) {
            int idx = tid + 256 * j;
            int r   = idx >> 2;
            int c4  = (idx & 3) * 4;
            cp16(&sA[buf][r * SLD + c4], A + (size_t)(bm + r) * lda + k0 + c4);
            cp16(&sB[buf][r * SLD + c4], W + (size_t)(bn + r) * ldw + k0 + c4);
        }
        CP_COMMIT();
    };

    issue_tile(0, 0);

    const int nt = K / GBK;
    for (int t = 0; t < nt; t++) {
        const int buf = t & 1;
        if (t + 1 < nt) { issue_tile((t + 1) * GBK, buf ^ 1); CP_WAIT(1); }
        else            { CP_WAIT(0); }
        __syncthreads();

        #pragma unroll
        for (int ks = 0; ks < 2; ks++) {
            const int k8 = ks * 8;
            uint32_t afr[4][4], bfr[4][2];
            #pragma unroll
            for (int mf = 0; mf < 4; mf++) {
                int r = wm + mf * 16 + lr;
                int c = k8 + lc;
                afr[mf][0] = sA[buf][r * SLD + c];
                afr[mf][1] = sA[buf][(r + 8) * SLD + c];
                afr[mf][2] = sA[buf][r * SLD + c + 4];
                afr[mf][3] = sA[buf][(r + 8) * SLD + c + 4];
            }
            #pragma unroll
            for (int nf = 0; nf < 4; nf++) {
                int n = wn + nf * 8 + lr;
                int k = k8 + lc;
                bfr[nf][0] = sB[buf][n * SLD + k];
                bfr[nf][1] = sB[buf][n * SLD + k + 4];
            }
            #pragma unroll
            for (int mf = 0; mf < 4; mf++)
                #pragma unroll
                for (int nf = 0; nf < 4; nf++)
                    mma_tf32(acc[mf][nf], afr[mf], bfr[nf]);
        }
        __syncthreads();
    }

    #pragma unroll
    for (int mf = 0; mf < 4; mf++) {
        const int row = bm + wm + mf * 16 + lr;
        #pragma unroll
        for (int nf = 0; nf < 4; nf++) {
            const int col = bn + wn + nf * 8 + lc * 2;
            float b0 = bias[col], b1 = bias[col + 1];
            float v0 = fmaxf(acc[mf][nf][0] + b0, 0.f);
            float v1 = fmaxf(acc[mf][nf][1] + b1, 0.f);
            float v2 = fmaxf(acc[mf][nf][2] + b0, 0.f);
            float v3 = fmaxf(acc[mf][nf][3] + b1, 0.f);
            if (round_out) { v0 = f2tff(v0); v1 = f2tff(v1); v2 = f2tff(v2); v3 = f2tff(v3); }
            *(float2*)(C + (size_t)row * ldc + col)       = make_float2(v0, v1);
            *(float2*)(C + (size_t)(row + 8) * ldc + col) = make_float2(v2, v3);
        }
    }
}

// ============================================================================
// Same pipeline + fused final GEMV epilogue: out[row] += relu(..) . w2
// ============================================================================
__global__ __launch_bounds__(256)
void gemm_tf32_final(const float* __restrict__ A, int lda,
                     const float* __restrict__ W, int ldw,
                     const float* __restrict__ bias,
                     const float* __restrict__ w2,
                     float* __restrict__ out,
                     int K)
{
    __shared__ uint32_t sA[2][GTM * SLD];
    __shared__ uint32_t sB[2][GTN * SLD];

    const int tid  = threadIdx.x;
    const int bm   = blockIdx.y * GTM;
    const int bn   = blockIdx.x * GTN;
    const int wid  = tid >> 5;
    const int lane = tid & 31;
    const int wm   = (wid >> 2) * 64;
    const int wn   = (wid & 3) * 32;
    const int lr   = lane >> 2;
    const int lc   = lane & 3;

    float acc[4][4][4];
    #pragma unroll
    for (int i = 0; i < 4; i++)
        #pragma unroll
        for (int j = 0; j < 4; j++)
            #pragma unroll
            for (int k = 0; k < 4; k++) acc[i][j][k] = 0.f;

    auto issue_tile = [&](int k0, int buf) {
        #pragma unroll
        for (int j = 0; j < 2; j++) {
            int idx = tid + 256 * j;
            int r   = idx >> 2;
            int c4  = (idx & 3) * 4;
            cp16(&sA[buf][r * SLD + c4], A + (size_t)(bm + r) * lda + k0 + c4);
            cp16(&sB[buf][r * SLD + c4], W + (size_t)(bn + r) * ldw + k0 + c4);
        }
        CP_COMMIT();
    };

    issue_tile(0, 0);

    const int nt = K / GBK;
    for (int t = 0; t < nt; t++) {
        const int buf = t & 1;
        if (t + 1 < nt) { issue_tile((t + 1) * GBK, buf ^ 1); CP_WAIT(1); }
        else            { CP_WAIT(0); }
        __syncthreads();

        #pragma unroll
        for (int ks = 0; ks < 2; ks++) {
            const int k8 = ks * 8;
            uint32_t afr[4][4], bfr[4][2];
            #pragma unroll
            for (int mf = 0; mf < 4; mf++) {
                int r = wm + mf * 16 + lr;
                int c = k8 + lc;
                afr[mf][0] = sA[buf][r * SLD + c];
                afr[mf][1] = sA[buf][(r + 8) * SLD + c];
                afr[mf][2] = sA[buf][r * SLD + c + 4];
                afr[mf][3] = sA[buf][(r + 8) * SLD + c + 4];
            }
            #pragma unroll
            for (int nf = 0; nf < 4; nf++) {
                int n = wn + nf * 8 + lr;
                int k = k8 + lc;
                bfr[nf][0] = sB[buf][n * SLD + k];
                bfr[nf][1] = sB[buf][n * SLD + k + 4];
            }
            #pragma unroll
            for (int mf = 0; mf < 4; mf++)
                #pragma unroll
                for (int nf = 0; nf < 4; nf++)
                    mma_tf32(acc[mf][nf], afr[mf], bfr[nf]);
        }
        __syncthreads();
    }

    #pragma unroll
    for (int mf = 0; mf < 4; mf++) {
        const int row = bm + wm + mf * 16 + lr;
        float p0 = 0.f, p1 = 0.f;
        #pragma unroll
        for (int nf = 0; nf < 4; nf++) {
            const int col = bn + wn + nf * 8 + lc * 2;
            float b0 = bias[col], b1 = bias[col + 1];
            float w0 = w2[col],   w1 = w2[col + 1];
            float v0 = fmaxf(acc[mf][nf][0] + b0, 0.f);
            float v1 = fmaxf(acc[mf][nf][1] + b1, 0.f);
            float v2 = fmaxf(acc[mf][nf][2] + b0, 0.f);
            float v3 = fmaxf(acc[mf][nf][3] + b1, 0.f);
            p0 = fmaf(v0, w0, fmaf(v1, w1, p0));
            p1 = fmaf(v2, w0, fmaf(v3, w1, p1));
        }
        atomicAdd(&out[row], p0);
        atomicAdd(&out[row + 8], p1);
    }
}

// ============================================================================
// TF32 GEMM 64x64 (bot2): cp.async 2-stage, 8 warps (2x4), warp tile 32x16
// ============================================================================
__global__ __launch_bounds__(256)
void gemm_tf32_64(const float* __restrict__ A, int lda,
                  const float* __restrict__ W, int ldw,
                  const float* __restrict__ bias,
                  float* __restrict__ C, int ldc,
                  int K)
{
    __shared__ uint32_t sA[2][64 * SLD];
    __shared__ uint32_t sB[2][64 * SLD];

    const int tid  = threadIdx.x;
    const int bm   = blockIdx.y * 64;
    const int wid  = tid >> 5;
    const int lane = tid & 31;
    const int wm   = (wid >> 2) * 32;
    const int wn   = (wid & 3) * 16;
    const int lr   = lane >> 2;
    const int lc   = lane & 3;

    float acc[2][2][4];
    #pragma unroll
    for (int i = 0; i < 2; i++)
        #pragma unroll
        for (int j = 0; j < 2; j++)
            #pragma unroll
            for (int k = 0; k < 4; k++) acc[i][j][k] = 0.f;

    auto issue_tile = [&](int k0, int buf) {
        int r  = tid >> 2;
        int c4 = (tid & 3) * 4;
        cp16(&sA[buf][r * SLD + c4], A + (size_t)(bm + r) * lda + k0 + c4);
        cp16(&sB[buf][r * SLD + c4], W + (size_t)r * ldw + k0 + c4);
        CP_COMMIT();
    };

    issue_tile(0, 0);

    const int nt = K / GBK;
    for (int t = 0; t < nt; t++) {
        const int buf = t & 1;
        if (t + 1 < nt) { issue_tile((t + 1) * GBK, buf ^ 1); CP_WAIT(1); }
        else            { CP_WAIT(0); }
        __syncthreads();

        #pragma unroll
        for (int ks = 0; ks < 2; ks++) {
            const int k8 = ks * 8;
            uint32_t afr[2][4], bfr[2][2];
            #pragma unroll
            for (int mf = 0; mf < 2; mf++) {
                int r = wm + mf * 16 + lr;
                int c = k8 + lc;
                afr[mf][0] = sA[buf][r * SLD + c];
                afr[mf][1] = sA[buf][(r + 8) * SLD + c];
                afr[mf][2] = sA[buf][r * SLD + c + 4];
                afr[mf][3] = sA[buf][(r + 8) * SLD + c + 4];
            }
            #pragma unroll
            for (int nf = 0; nf < 2; nf++) {
                int n = wn + nf * 8 + lr;
                int k = k8 + lc;
                bfr[nf][0] = sB[buf][n * SLD + k];
                bfr[nf][1] = sB[buf][n * SLD + k + 4];
            }
            #pragma unroll
            for (int mf = 0; mf < 2; mf++)
                #pragma unroll
                for (int nf = 0; nf < 2; nf++)
                    mma_tf32(acc[mf][nf], afr[mf], bfr[nf]);
        }
        __syncthreads();
    }

    #pragma unroll
    for (int mf = 0; mf < 2; mf++) {
        const int row = bm + wm + mf * 16 + lr;
        #pragma unroll
        for (int nf = 0; nf < 2; nf++) {
            const int col = wn + nf * 8 + lc * 2;
            float b0 = bias[col], b1 = bias[col + 1];
            float v0 = f2tff(fmaxf(acc[mf][nf][0] + b0, 0.f));
            float v1 = f2tff(fmaxf(acc[mf][nf][1] + b1, 0.f));
            float v2 = f2tff(fmaxf(acc[mf][nf][2] + b0, 0.f));
            float v3 = f2tff(fmaxf(acc[mf][nf][3] + b1, 0.f));
            *(float2*)(C + (size_t)row * ldc + col)       = make_float2(v0, v1);
            *(float2*)(C + (size_t)(row + 8) * ldc + col) = make_float2(v2, v3);
        }
    }
}

// ---------------- bot0: x1 = tf32(relu(dense_x @ bw0^T + b0)), K=13 --------
// 32 batch rows per block (measured best)
__global__ __launch_bounds__(256)
void bot0_kernel(const float* __restrict__ x, const float* __restrict__ w,
                 const float* __restrict__ bias, float* __restrict__ out)
{
    __shared__ float sw[13][512];
    __shared__ float sb[512];
    __shared__ float sx[32][13];

    const int tid = threadIdx.x;
    for (int i = tid; i < 512 * 13; i += 256) {
        int c = i % 512, k = i / 512;
        sw[k][c] = w[c * 13 + k];
    }
    for (int i = tid; i < 512; i += 256) sb[i] = bias[i];
    for (int i = tid; i < 32 * 13; i += 256) {
        int r = i / 13, k = i % 13;
        sx[r][k] = x[(size_t)(blockIdx.x * 32 + r) * 13 + k];
    }
    __syncthreads();

    const int c0 = tid * 2;
    #pragma unroll 4
    for (int r = 0; r < 32; r++) {
        float a0 = sb[c0], a1 = sb[c0 + 1];
        #pragma unroll
        for (int k = 0; k < 13; k++) {
            float xv = sx[r][k];
            a0 = fmaf(xv, sw[k][c0],     a0);
            a1 = fmaf(xv, sw[k][c0 + 1], a1);
        }
        a0 = f2tff(fmaxf(a0, 0.f)); a1 = f2tff(fmaxf(a1, 0.f));
        *(float2*)(out + (size_t)(blockIdx.x * 32 + r) * 512 + c0) = make_float2(a0, a1);
    }
}

// ---------------- single merged prep kernel (side stream, first) -----------
// w1c (131072) + w2c (16384) + w0p (212992) + wt1c (131072) + out (8192)
#define PREP_N1 (256 * 512)
#define PREP_N2 (PREP_N1 + 64 * 256)
#define PREP_N3 (PREP_N2 + 512 * RLD)
#define PREP_N4 (PREP_N3 + 256 * 512)
#define PREP_N5 (PREP_N4 + BATCH)

__global__ __launch_bounds__(256)
void prep_all_kernel(const float* __restrict__ bw1, const float* __restrict__ bw2,
                     const float* __restrict__ tw0, const float* __restrict__ tw1,
                     const float* __restrict__ tb2,
                     float* __restrict__ w1c, float* __restrict__ w2c,
                     float* __restrict__ w0p, float* __restrict__ wt1c,
                     float* __restrict__ out)
{
    int i = blockIdx.x * 256 + threadIdx.x;
    if (i < PREP_N1) {
        w1c[i] = f2tff(bw1[i]);
    } else if (i < PREP_N2) {
        int j = i - PREP_N1;
        w2c[j] = f2tff(bw2[j]);
    } else if (i < PREP_N3) {
        int j = i - PREP_N2;
        int n = j / RLD, k = j % RLD;
        w0p[j] = (k < RDIM) ? f2tff(tw0[n * RDIM + k]) : 0.f;
    } else if (i < PREP_N4) {
        int j = i - PREP_N3;
        wt1c[j] = f2tff(tw1[j]);
    } else if (i < PREP_N5) {
        out[i - PREP_N4] = tb2[0];
    }
}

// ---------------- embedding gather + mean-pool, 2 samples/warp (MLP=8) -----
__global__ __launch_bounds__(256)
void emb_pool_kernel(const int* __restrict__ lS_i,
                     const float* __restrict__ tables,
                     float* __restrict__ feat)
{
    const int t    = blockIdx.y;
    const int w    = threadIdx.x >> 5;
    const int lane = threadIdx.x & 31;
    const int b0   = blockIdx.x * 16 + w * 2;

    const float* tab = tables + (size_t)t * ROWS_T * EDIM;
    const int*   idx = lS_i + (size_t)t * BATCH * POOL_L + (size_t)b0 * POOL_L;

    int r[8];
    #pragma unroll
    for (int l = 0; l < 8; l++) r[l] = idx[l];

    float2 v[8];
    #pragma unroll
    for (int l = 0; l < 8; l++)
        v[l] = *(const float2*)(tab + (size_t)r[l] * EDIM + lane * 2);

    float2 a0 = make_float2(v[0].x + v[1].x + v[2].x + v[3].x,
                            v[0].y + v[1].y + v[2].y + v[3].y);
    float2 a1 = make_float2(v[4].x + v[5].x + v[6].x + v[7].x,
                            v[4].y + v[5].y + v[6].y + v[7].y);
    a0.x = f2tff(a0.x * 0.25f); a0.y = f2tff(a0.y * 0.25f);
    a1.x = f2tff(a1.x * 0.25f); a1.y = f2tff(a1.y * 0.25f);

    size_t off = (size_t)(t + 1) * EDIM + lane * 2;
    *(float2*)(feat + (size_t)b0 * FEAT_LD + off)       = a0;
    *(float2*)(feat + (size_t)(b0 + 1) * FEAT_LD + off) = a1;
}

// ============================================================================
// Interaction: Z = F F^T per sample (feat already tf32-rounded -> raw copy)
// ============================================================================
#define ISLD 68

__global__ __launch_bounds__(128)
void interact_mma(const float* __restrict__ feat, float* __restrict__ R)
{
    __shared__ uint32_t s[4][32 * ISLD];

    const int wid  = threadIdx.x >> 5;
    const int lane = threadIdx.x & 31;
    const int b    = blockIdx.x * 4 + wid;
    const int lr   = lane >> 2;
    const int lc   = lane & 3;

    const float* fb = feat + (size_t)b * FEAT_LD;
    uint32_t* ss = s[wid];

    for (int i = lane; i < NFEAT * 16; i += 32) {
        int r  = i >> 4;
        int c4 = (i & 15) * 4;
        *(uint4*)&ss[r * ISLD + c4] = *(const uint4*)(fb + r * EDIM + c4);
    }
    for (int i = lane; i < 5 * 16; i += 32) {
        int r  = NFEAT + (i >> 4);
        int c4 = (i & 15) * 4;
        *(uint4*)&ss[r * ISLD + c4] = make_uint4(0, 0, 0, 0);
    }
    __syncwarp();

    float acc[2][4][4];
    #pragma unroll
    for (int i = 0; i < 2; i++)
        #pragma unroll
        for (int j = 0; j < 4; j++)
            #pragma unroll
            for (int k = 0; k < 4; k++) acc[i][j][k] = 0.f;

    #pragma unroll
    for (int k8 = 0; k8 < EDIM; k8 += 8) {
        uint32_t afr[2][4], bfr[4][2];
        #pragma unroll
        for (int mf = 0; mf < 2; mf++) {
            int r = mf * 16 + lr;
            int c = k8 + lc;
            afr[mf][0] = ss[r * ISLD + c];
            afr[mf][1] = ss[(r + 8) * ISLD + c];
            afr[mf][2] = ss[r * ISLD + c + 4];
            afr[mf][3] = ss[(r + 8) * ISLD + c + 4];
        }
        #pragma unroll
        for (int nf = 0; nf < 4; nf++) {
            int n = nf * 8 + lr;
            int k = k8 + lc;
            bfr[nf][0] = ss[n * ISLD + k];
            bfr[nf][1] = ss[n * ISLD + k + 4];
        }
        #pragma unroll
        for (int mf = 0; mf < 2; mf++)
            #pragma unroll
            for (int nf = 0; nf < 4; nf++)
                mma_tf32(acc[mf][nf], afr[mf], bfr[nf]);
    }

    float* Rb = R + (size_t)b * RLD;
    Rb[lane]      = fb[lane];
    Rb[lane + 32] = fb[lane + 32];
    if (lane == 0) Rb[RDIM] = 0.f;

    #pragma unroll
    for (int mf = 0; mf < 2; mf++) {
        #pragma unroll
        for (int nf = 0; nf < 4; nf++) {
            int r0 = mf * 16 + lr, r1 = r0 + 8;
            int c0 = nf * 8 + lc * 2, c1 = c0 + 1;
            if (r0 < NFEAT && c0 < r0) Rb[EDIM + r0 * (r0 - 1) / 2 + c0] = f2tff(acc[mf][nf][0]);
            if (r0 < NFEAT && c1 < r0) Rb[EDIM + r0 * (r0 - 1) / 2 + c1] = f2tff(acc[mf][nf][1]);
            if (r1 < NFEAT && c0 < r1) Rb[EDIM + r1 * (r1 - 1) / 2 + c0] = f2tff(acc[mf][nf][2]);
            if (r1 < NFEAT && c1 < r1) Rb[EDIM + r1 * (r1 - 1) / 2 + c1] = f2tff(acc[mf][nf][3]);
        }
    }
}

// ---------------- launcher --------------------------------------------------
extern "C" void kernel_launch(void* const* d_in, const int* in_sizes, int n_in,
                              void* d_out, int out_size)
{
    const float* dense_x = (const float*)d_in[0];
    const int*   lS_i    = (const int*)d_in[2];
    const float* emb     = (const float*)d_in[3];
    const float *bw0 = (const float*)d_in[4],  *bb0 = (const float*)d_in[5];
    const float *bw1 = (const float*)d_in[6],  *bb1 = (const float*)d_in[7];
    const float *bw2 = (const float*)d_in[8],  *bb2 = (const float*)d_in[9];
    const float *tw0 = (const float*)d_in[10], *tb0 = (const float*)d_in[11];
    const float *tw1 = (const float*)d_in[12], *tb1 = (const float*)d_in[13];
    const float *tw2 = (const float*)d_in[14], *tb2 = (const float*)d_in[15];
    float* out = (float*)d_out;

    float *x1, *x2, *feat, *R, *z1, *w0p, *w1c, *w2c, *wt1c;
    cudaGetSymbolAddress((void**)&x1,   g_x1);
    cudaGetSymbolAddress((void**)&x2,   g_x2);
    cudaGetSymbolAddress((void**)&feat, g_feat);
    cudaGetSymbolAddress((void**)&R,    g_R);
    cudaGetSymbolAddress((void**)&z1,   g_z1);
    cudaGetSymbolAddress((void**)&w0p,  g_w0p);
    cudaGetSymbolAddress((void**)&w1c,  g_w1c);
    cudaGetSymbolAddress((void**)&w2c,  g_w2c);
    cudaGetSymbolAddress((void**)&wt1c, g_wt1c);

    static cudaStream_t s1 = nullptr;
    static cudaEvent_t evFork = nullptr, evPrep = nullptr, evJoin = nullptr;
    if (!s1) {
        cudaStreamCreateWithFlags(&s1, cudaStreamNonBlocking);
        cudaEventCreateWithFlags(&evFork, cudaEventDisableTiming);
        cudaEventCreateWithFlags(&evPrep, cudaEventDisableTiming);
        cudaEventCreateWithFlags(&evJoin, cudaEventDisableTiming);
    }

    dim3 blk(256);

    // fork: ALL weight prep first (so main can grab it early), then embedding
    cudaEventRecord(evFork, 0);
    cudaStreamWaitEvent(s1, evFork, 0);
    prep_all_kernel<<<(PREP_N5 + 255) / 256, blk, 0, s1>>>(bw1, bw2, tw0, tw1, tb2,
                                                           w1c, w2c, w0p, wt1c, out);
    cudaEventRecord(evPrep, s1);
    emb_pool_kernel<<<dim3(BATCH / 16, N_TABLES), blk, 0, s1>>>(lS_i, emb, feat);
    cudaEventRecord(evJoin, s1);

    // main stream: bottom MLP chain (bot0 needs no prep; bot1 waits on evPrep)
    bot0_kernel<<<BATCH / 32, blk>>>(dense_x, bw0, bb0, x1);
    cudaStreamWaitEvent(0, evPrep, 0);
    gemm_tf32<<<dim3(256 / GTN, BATCH / GTM), blk>>>(x1, 512, w1c, 512, bb1, x2, 256, 512, 1);
    gemm_tf32_64<<<dim3(1, BATCH / 64), blk>>>(x2, 256, w2c, 256, bb2, feat, FEAT_LD, 256);

    // join: interact needs feat rows 1..26 from emb
    cudaStreamWaitEvent(0, evJoin, 0);

    interact_mma<<<BATCH / 4, 128>>>(feat, R);

    // top MLP: 416(pad) -> 512 -> 256 -> 1 (final GEMV fused)
    gemm_tf32<<<dim3(512 / GTN, BATCH / GTM), blk>>>(R, RLD, w0p, RLD, tb0, z1, 512, RLD, 1);
    gemm_tf32_final<<<dim3(256 / GTN, BATCH / GTM), blk>>>(z1, 512, wt1c, 512, tb1, tw2, out, 512);
}

// round 14
// speedup vs baseline: 1.0207x; 1.0207x over previous
#include <cuda_runtime.h>
#include <cuda_bf16.h>
#include <math.h>
#include <stdint.h>

#define N_TABLES 26
#define ROWS_T   100001
#define EDIM     64
#define BATCH    8192
#define POOL_L   4
#define NFEAT    (N_TABLES + 1)            // 27
#define NPAIRS   (NFEAT * (NFEAT - 1) / 2) // 351
#define RDIM     (EDIM + NPAIRS)           // 415
#define RLD      416                       // padded row stride for R
#define FEAT_LD  (NFEAT * EDIM)            // 1728

// ---------------- scratch (device globals; no allocation allowed) ----------
__device__ float g_x1[BATCH * 512];
__device__ float g_x2[BATCH * 256];
__device__ float g_feat[BATCH * FEAT_LD];
__device__ float g_R[BATCH * RLD];
__device__ float g_z1[BATCH * 512];
__device__ float g_w0p[512 * RLD];          // top_w0 padded + tf32-rounded
__device__ float g_w1c[256 * 512];          // bot_w1 tf32-rounded
__device__ float g_w2c[64 * 256];           // bot_w2 tf32-rounded
__device__ float g_wt1c[256 * 512];         // top_w1 tf32-rounded

// ---------------- tf32 helpers ---------------------------------------------
__device__ __forceinline__ uint32_t f2tf(float f) {
    uint32_t u;
    asm("cvt.rna.tf32.f32 %0, %1;" : "=r"(u) : "f"(f));
    return u;
}
__device__ __forceinline__ float f2tff(float f) { return __uint_as_float(f2tf(f)); }

__device__ __forceinline__ void mma_tf32(float* c, const uint32_t* a, const uint32_t* b) {
    asm volatile(
        "mma.sync.aligned.m16n8k8.row.col.f32.tf32.tf32.f32 "
        "{%0,%1,%2,%3}, {%4,%5,%6,%7}, {%8,%9}, {%0,%1,%2,%3};"
        : "+f"(c[0]), "+f"(c[1]), "+f"(c[2]), "+f"(c[3])
        : "r"(a[0]), "r"(a[1]), "r"(a[2]), "r"(a[3]), "r"(b[0]), "r"(b[1]));
}

__device__ __forceinline__ void cp16(void* smem_dst, const void* gsrc) {
    uint32_t s = (uint32_t)__cvta_generic_to_shared(smem_dst);
    asm volatile("cp.async.cg.shared.global [%0], [%1], 16;" :: "r"(s), "l"(gsrc));
}
#define CP_COMMIT()  asm volatile("cp.async.commit_group;")
#define CP_WAIT(n)   asm volatile("cp.async.wait_group %0;" :: "n"(n))

// ============================================================================
// TF32 GEMM 128x128, cp.async double-buffered, 2 CTAs/SM forced.
// Inputs must be tf32-rounded. C = relu(A @ W^T + bias).
// ============================================================================
#define GTM 128
#define GTN 128
#define GBK 16
#define SLD 20

__global__ __launch_bounds__(256, 2)
void gemm_tf32(const float* __restrict__ A, int lda,
               const float* __restrict__ W, int ldw,
               const float* __restrict__ bias,
               float* __restrict__ C, int ldc,
               int K, int round_out)
{
    __shared__ uint32_t sA[2][GTM * SLD];
    __shared__ uint32_t sB[2][GTN * SLD];

    const int tid  = threadIdx.x;
    const int bm   = blockIdx.y * GTM;
    const int bn   = blockIdx.x * GTN;
    const int wid  = tid >> 5;
    const int lane = tid & 31;
    const int wm   = (wid >> 2) * 64;
    const int wn   = (wid & 3) * 32;
    const int lr   = lane >> 2;
    const int lc   = lane & 3;

    float acc[4][4][4];
    #pragma unroll
    for (int i = 0; i < 4; i++)
        #pragma unroll
        for (int j = 0; j < 4; j++)
            #pragma unroll
            for (int k = 0; k < 4; k++) acc[i][j][k] = 0.f;

    auto issue_tile = [&](int k0, int buf) {
        #pragma unroll
        for (int j = 0; j < 2; j++) {
            int idx = tid + 256 * j;
            int r   = idx >> 2;
            int c4  = (idx & 3) * 4;
            cp16(&sA[buf][r * SLD + c4], A + (size_t)(bm + r) * lda + k0 + c4);
            cp16(&sB[buf][r * SLD + c4], W + (size_t)(bn + r) * ldw + k0 + c4);
        }
        CP_COMMIT();
    };

    issue_tile(0, 0);

    const int nt = K / GBK;
    for (int t = 0; t < nt; t++) {
        const int buf = t & 1;
        if (t + 1 < nt) { issue_tile((t + 1) * GBK, buf ^ 1); CP_WAIT(1); }
        else            { CP_WAIT(0); }
        __syncthreads();

        #pragma unroll
        for (int ks = 0; ks < 2; ks++) {
            const int k8 = ks * 8;
            uint32_t afr[4][4], bfr[4][2];
            #pragma unroll
            for (int mf = 0; mf < 4; mf++) {
                int r = wm + mf * 16 + lr;
                int c = k8 + lc;
                afr[mf][0] = sA[buf][r * SLD + c];
                afr[mf][1] = sA[buf][(r + 8) * SLD + c];
                afr[mf][2] = sA[buf][r * SLD + c + 4];
                afr[mf][3] = sA[buf][(r + 8) * SLD + c + 4];
            }
            #pragma unroll
            for (int nf = 0; nf < 4; nf++) {
                int n = wn + nf * 8 + lr;
                int k = k8 + lc;
                bfr[nf][0] = sB[buf][n * SLD + k];
                bfr[nf][1] = sB[buf][n * SLD + k + 4];
            }
            #pragma unroll
            for (int mf = 0; mf < 4; mf++)
                #pragma unroll
                for (int nf = 0; nf < 4; nf++)
                    mma_tf32(acc[mf][nf], afr[mf], bfr[nf]);
        }
        __syncthreads();
    }

    #pragma unroll
    for (int mf = 0; mf < 4; mf++) {
        const int row = bm + wm + mf * 16 + lr;
        #pragma unroll
        for (int nf = 0; nf < 4; nf++) {
            const int col = bn + wn + nf * 8 + lc * 2;
            float b0 = bias[col], b1 = bias[col + 1];
            float v0 = fmaxf(acc[mf][nf][0] + b0, 0.f);
            float v1 = fmaxf(acc[mf][nf][1] + b1, 0.f);
            float v2 = fmaxf(acc[mf][nf][2] + b0, 0.f);
            float v3 = fmaxf(acc[mf][nf][3] + b1, 0.f);
            if (round_out) { v0 = f2tff(v0); v1 = f2tff(v1); v2 = f2tff(v2); v3 = f2tff(v3); }
            *(float2*)(C + (size_t)row * ldc + col)       = make_float2(v0, v1);
            *(float2*)(C + (size_t)(row + 8) * ldc + col) = make_float2(v2, v3);
        }
    }
}

// ============================================================================
// Same pipeline + fused final GEMV epilogue: out[row] += relu(..) . w2
// ============================================================================
__global__ __launch_bounds__(256, 2)
void gemm_tf32_final(const float* __restrict__ A, int lda,
                     const float* __restrict__ W, int ldw,
                     const float* __restrict__ bias,
                     const float* __restrict__ w2,
                     float* __restrict__ out,
                     int K)
{
    __shared__ uint32_t sA[2][GTM * SLD];
    __shared__ uint32_t sB[2][GTN * SLD];

    const int tid  = threadIdx.x;
    const int bm   = blockIdx.y * GTM;
    const int bn   = blockIdx.x * GTN;
    const int wid  = tid >> 5;
    const int lane = tid & 31;
    const int wm   = (wid >> 2) * 64;
    const int wn   = (wid & 3) * 32;
    const int lr   = lane >> 2;
    const int lc   = lane & 3;

    float acc[4][4][4];
    #pragma unroll
    for (int i = 0; i < 4; i++)
        #pragma unroll
        for (int j = 0; j < 4; j++)
            #pragma unroll
            for (int k = 0; k < 4; k++) acc[i][j][k] = 0.f;

    auto issue_tile = [&](int k0, int buf) {
        #pragma unroll
        for (int j = 0; j < 2; j++) {
            int idx = tid + 256 * j;
            int r   = idx >> 2;
            int c4  = (idx & 3) * 4;
            cp16(&sA[buf][r * SLD + c4], A + (size_t)(bm + r) * lda + k0 + c4);
            cp16(&sB[buf][r * SLD + c4], W + (size_t)(bn + r) * ldw + k0 + c4);
        }
        CP_COMMIT();
    };

    issue_tile(0, 0);

    const int nt = K / GBK;
    for (int t = 0; t < nt; t++) {
        const int buf = t & 1;
        if (t + 1 < nt) { issue_tile((t + 1) * GBK, buf ^ 1); CP_WAIT(1); }
        else            { CP_WAIT(0); }
        __syncthreads();

        #pragma unroll
        for (int ks = 0; ks < 2; ks++) {
            const int k8 = ks * 8;
            uint32_t afr[4][4], bfr[4][2];
            #pragma unroll
            for (int mf = 0; mf < 4; mf++) {
                int r = wm + mf * 16 + lr;
                int c = k8 + lc;
                afr[mf][0] = sA[buf][r * SLD + c];
                afr[mf][1] = sA[buf][(r + 8) * SLD + c];
                afr[mf][2] = sA[buf][r * SLD + c + 4];
                afr[mf][3] = sA[buf][(r + 8) * SLD + c + 4];
            }
            #pragma unroll
            for (int nf = 0; nf < 4; nf++) {
                int n = wn + nf * 8 + lr;
                int k = k8 + lc;
                bfr[nf][0] = sB[buf][n * SLD + k];
                bfr[nf][1] = sB[buf][n * SLD + k + 4];
            }
            #pragma unroll
            for (int mf = 0; mf < 4; mf++)
                #pragma unroll
                for (int nf = 0; nf < 4; nf++)
                    mma_tf32(acc[mf][nf], afr[mf], bfr[nf]);
        }
        __syncthreads();
    }

    #pragma unroll
    for (int mf = 0; mf < 4; mf++) {
        const int row = bm + wm + mf * 16 + lr;
        float p0 = 0.f, p1 = 0.f;
        #pragma unroll
        for (int nf = 0; nf < 4; nf++) {
            const int col = bn + wn + nf * 8 + lc * 2;
            float b0 = bias[col], b1 = bias[col + 1];
            float w0 = w2[col],   w1 = w2[col + 1];
            float v0 = fmaxf(acc[mf][nf][0] + b0, 0.f);
            float v1 = fmaxf(acc[mf][nf][1] + b1, 0.f);
            float v2 = fmaxf(acc[mf][nf][2] + b0, 0.f);
            float v3 = fmaxf(acc[mf][nf][3] + b1, 0.f);
            p0 = fmaf(v0, w0, fmaf(v1, w1, p0));
            p1 = fmaf(v2, w0, fmaf(v3, w1, p1));
        }
        atomicAdd(&out[row], p0);
        atomicAdd(&out[row + 8], p1);
    }
}

// ============================================================================
// TF32 GEMM 64x64 (bot2): cp.async 2-stage, 8 warps (2x4), warp tile 32x16
// ============================================================================
__global__ __launch_bounds__(256)
void gemm_tf32_64(const float* __restrict__ A, int lda,
                  const float* __restrict__ W, int ldw,
                  const float* __restrict__ bias,
                  float* __restrict__ C, int ldc,
                  int K)
{
    __shared__ uint32_t sA[2][64 * SLD];
    __shared__ uint32_t sB[2][64 * SLD];

    const int tid  = threadIdx.x;
    const int bm   = blockIdx.y * 64;
    const int wid  = tid >> 5;
    const int lane = tid & 31;
    const int wm   = (wid >> 2) * 32;
    const int wn   = (wid & 3) * 16;
    const int lr   = lane >> 2;
    const int lc   = lane & 3;

    float acc[2][2][4];
    #pragma unroll
    for (int i = 0; i < 2; i++)
        #pragma unroll
        for (int j = 0; j < 2; j++)
            #pragma unroll
            for (int k = 0; k < 4; k++) acc[i][j][k] = 0.f;

    auto issue_tile = [&](int k0, int buf) {
        int r  = tid >> 2;
        int c4 = (tid & 3) * 4;
        cp16(&sA[buf][r * SLD + c4], A + (size_t)(bm + r) * lda + k0 + c4);
        cp16(&sB[buf][r * SLD + c4], W + (size_t)r * ldw + k0 + c4);
        CP_COMMIT();
    };

    issue_tile(0, 0);

    const int nt = K / GBK;
    for (int t = 0; t < nt; t++) {
        const int buf = t & 1;
        if (t + 1 < nt) { issue_tile((t + 1) * GBK, buf ^ 1); CP_WAIT(1); }
        else            { CP_WAIT(0); }
        __syncthreads();

        #pragma unroll
        for (int ks = 0; ks < 2; ks++) {
            const int k8 = ks * 8;
            uint32_t afr[2][4], bfr[2][2];
            #pragma unroll
            for (int mf = 0; mf < 2; mf++) {
                int r = wm + mf * 16 + lr;
                int c = k8 + lc;
                afr[mf][0] = sA[buf][r * SLD + c];
                afr[mf][1] = sA[buf][(r + 8) * SLD + c];
                afr[mf][2] = sA[buf][r * SLD + c + 4];
                afr[mf][3] = sA[buf][(r + 8) * SLD + c + 4];
            }
            #pragma unroll
            for (int nf = 0; nf < 2; nf++) {
                int n = wn + nf * 8 + lr;
                int k = k8 + lc;
                bfr[nf][0] = sB[buf][n * SLD + k];
                bfr[nf][1] = sB[buf][n * SLD + k + 4];
            }
            #pragma unroll
            for (int mf = 0; mf < 2; mf++)
                #pragma unroll
                for (int nf = 0; nf < 2; nf++)
                    mma_tf32(acc[mf][nf], afr[mf], bfr[nf]);
        }
        __syncthreads();
    }

    #pragma unroll
    for (int mf = 0; mf < 2; mf++) {
        const int row = bm + wm + mf * 16 + lr;
        #pragma unroll
        for (int nf = 0; nf < 2; nf++) {
            const int col = wn + nf * 8 + lc * 2;
            float b0 = bias[col], b1 = bias[col + 1];
            float v0 = f2tff(fmaxf(acc[mf][nf][0] + b0, 0.f));
            float v1 = f2tff(fmaxf(acc[mf][nf][1] + b1, 0.f));
            float v2 = f2tff(fmaxf(acc[mf][nf][2] + b0, 0.f));
            float v3 = f2tff(fmaxf(acc[mf][nf][3] + b1, 0.f));
            *(float2*)(C + (size_t)row * ldc + col)       = make_float2(v0, v1);
            *(float2*)(C + (size_t)(row + 8) * ldc + col) = make_float2(v2, v3);
        }
    }
}

// ---------------- bot0: x1 = tf32(relu(dense_x @ bw0^T + b0)), K=13 --------
__global__ __launch_bounds__(256)
void bot0_kernel(const float* __restrict__ x, const float* __restrict__ w,
                 const float* __restrict__ bias, float* __restrict__ out)
{
    __shared__ float sw[13][512];
    __shared__ float sb[512];
    __shared__ float sx[32][13];

    const int tid = threadIdx.x;
    for (int i = tid; i < 512 * 13; i += 256) {
        int c = i % 512, k = i / 512;
        sw[k][c] = w[c * 13 + k];
    }
    for (int i = tid; i < 512; i += 256) sb[i] = bias[i];
    for (int i = tid; i < 32 * 13; i += 256) {
        int r = i / 13, k = i % 13;
        sx[r][k] = x[(size_t)(blockIdx.x * 32 + r) * 13 + k];
    }
    __syncthreads();

    const int c0 = tid * 2;
    #pragma unroll 4
    for (int r = 0; r < 32; r++) {
        float a0 = sb[c0], a1 = sb[c0 + 1];
        #pragma unroll
        for (int k = 0; k < 13; k++) {
            float xv = sx[r][k];
            a0 = fmaf(xv, sw[k][c0],     a0);
            a1 = fmaf(xv, sw[k][c0 + 1], a1);
        }
        a0 = f2tff(fmaxf(a0, 0.f)); a1 = f2tff(fmaxf(a1, 0.f));
        *(float2*)(out + (size_t)(blockIdx.x * 32 + r) * 512 + c0) = make_float2(a0, a1);
    }
}

// ---------------- weight prep: tf32-rounded copies --------------------------
__global__ __launch_bounds__(256)
void cvt_copy_kernel(const float* __restrict__ src, float* __restrict__ dst, int n)
{
    int i = blockIdx.x * 256 + threadIdx.x;
    if (i < n) dst[i] = f2tff(src[i]);
}

__global__ __launch_bounds__(256)
void pad_w0_kernel(const float* __restrict__ w, float* __restrict__ wp)
{
    int i = blockIdx.x * 256 + threadIdx.x;
    if (i < 512 * RLD) {
        int n = i / RLD, k = i % RLD;
        wp[i] = (k < RDIM) ? f2tff(w[n * RDIM + k]) : 0.f;
    }
}

__global__ __launch_bounds__(256)
void out_init_kernel(float* __restrict__ out, const float* __restrict__ b)
{
    int i = blockIdx.x * 256 + threadIdx.x;
    if (i < BATCH) out[i] = b[0];
}

// ---------------- embedding gather + mean-pool, tf32-rounded output --------
__global__ __launch_bounds__(256)
void emb_pool_kernel(const int* __restrict__ lS_i,
                     const float* __restrict__ tables,
                     float* __restrict__ feat)
{
    const int t    = blockIdx.y;
    const int b    = blockIdx.x * 8 + (threadIdx.x >> 5);
    const int lane = threadIdx.x & 31;

    const float* tab = tables + (size_t)t * ROWS_T * EDIM;
    const int*   idx = lS_i + (size_t)t * BATCH * POOL_L + (size_t)b * POOL_L;

    float2 acc = make_float2(0.f, 0.f);
    #pragma unroll
    for (int l = 0; l < POOL_L; l++) {
        int r = idx[l];
        float2 v = *(const float2*)(tab + (size_t)r * EDIM + lane * 2);
        acc.x += v.x; acc.y += v.y;
    }
    acc.x = f2tff(acc.x * 0.25f); acc.y = f2tff(acc.y * 0.25f);
    *(float2*)(feat + (size_t)b * FEAT_LD + (size_t)(t + 1) * EDIM + lane * 2) = acc;
}

// ============================================================================
// Interaction: Z = F F^T per sample (feat already tf32-rounded -> raw copy)
// ============================================================================
#define ISLD 68

__global__ __launch_bounds__(128)
void interact_mma(const float* __restrict__ feat, float* __restrict__ R)
{
    __shared__ uint32_t s[4][32 * ISLD];

    const int wid  = threadIdx.x >> 5;
    const int lane = threadIdx.x & 31;
    const int b    = blockIdx.x * 4 + wid;
    const int lr   = lane >> 2;
    const int lc   = lane & 3;

    const float* fb = feat + (size_t)b * FEAT_LD;
    uint32_t* ss = s[wid];

    for (int i = lane; i < NFEAT * 16; i += 32) {
        int r  = i >> 4;
        int c4 = (i & 15) * 4;
        *(uint4*)&ss[r * ISLD + c4] = *(const uint4*)(fb + r * EDIM + c4);
    }
    for (int i = lane; i < 5 * 16; i += 32) {
        int r  = NFEAT + (i >> 4);
        int c4 = (i & 15) * 4;
        *(uint4*)&ss[r * ISLD + c4] = make_uint4(0, 0, 0, 0);
    }
    __syncwarp();

    float acc[2][4][4];
    #pragma unroll
    for (int i = 0; i < 2; i++)
        #pragma unroll
        for (int j = 0; j < 4; j++)
            #pragma unroll
            for (int k = 0; k < 4; k++) acc[i][j][k] = 0.f;

    #pragma unroll
    for (int k8 = 0; k8 < EDIM; k8 += 8) {
        uint32_t afr[2][4], bfr[4][2];
        #pragma unroll
        for (int mf = 0; mf < 2; mf++) {
            int r = mf * 16 + lr;
            int c = k8 + lc;
            afr[mf][0] = ss[r * ISLD + c];
            afr[mf][1] = ss[(r + 8) * ISLD + c];
            afr[mf][2] = ss[r * ISLD + c + 4];
            afr[mf][3] = ss[(r + 8) * ISLD + c + 4];
        }
        #pragma unroll
        for (int nf = 0; nf < 4; nf++) {
            int n = nf * 8 + lr;
            int k = k8 + lc;
            bfr[nf][0] = ss[n * ISLD + k];
            bfr[nf][1] = ss[n * ISLD + k + 4];
        }
        #pragma unroll
        for (int mf = 0; mf < 2; mf++)
            #pragma unroll
            for (int nf = 0; nf < 4; nf++)
                mma_tf32(acc[mf][nf], afr[mf], bfr[nf]);
    }

    float* Rb = R + (size_t)b * RLD;
    Rb[lane]      = fb[lane];
    Rb[lane + 32] = fb[lane + 32];
    if (lane == 0) Rb[RDIM] = 0.f;

    #pragma unroll
    for (int mf = 0; mf < 2; mf++) {
        #pragma unroll
        for (int nf = 0; nf < 4; nf++) {
            int r0 = mf * 16 + lr, r1 = r0 + 8;
            int c0 = nf * 8 + lc * 2, c1 = c0 + 1;
            if (r0 < NFEAT && c0 < r0) Rb[EDIM + r0 * (r0 - 1) / 2 + c0] = f2tff(acc[mf][nf][0]);
            if (r0 < NFEAT && c1 < r0) Rb[EDIM + r0 * (r0 - 1) / 2 + c1] = f2tff(acc[mf][nf][1]);
            if (r1 < NFEAT && c0 < r1) Rb[EDIM + r1 * (r1 - 1) / 2 + c0] = f2tff(acc[mf][nf][2]);
            if (r1 < NFEAT && c1 < r1) Rb[EDIM + r1 * (r1 - 1) / 2 + c1] = f2tff(acc[mf][nf][3]);
        }
    }
}

// ---------------- launcher (R11 layout) -------------------------------------
extern "C" void kernel_launch(void* const* d_in, const int* in_sizes, int n_in,
                              void* d_out, int out_size)
{
    const float* dense_x = (const float*)d_in[0];
    const int*   lS_i    = (const int*)d_in[2];
    const float* emb     = (const float*)d_in[3];
    const float *bw0 = (const float*)d_in[4],  *bb0 = (const float*)d_in[5];
    const float *bw1 = (const float*)d_in[6],  *bb1 = (const float*)d_in[7];
    const float *bw2 = (const float*)d_in[8],  *bb2 = (const float*)d_in[9];
    const float *tw0 = (const float*)d_in[10], *tb0 = (const float*)d_in[11];
    const float *tw1 = (const float*)d_in[12], *tb1 = (const float*)d_in[13];
    const float *tw2 = (const float*)d_in[14], *tb2 = (const float*)d_in[15];
    float* out = (float*)d_out;

    float *x1, *x2, *feat, *R, *z1, *w0p, *w1c, *w2c, *wt1c;
    cudaGetSymbolAddress((void**)&x1,   g_x1);
    cudaGetSymbolAddress((void**)&x2,   g_x2);
    cudaGetSymbolAddress((void**)&feat, g_feat);
    cudaGetSymbolAddress((void**)&R,    g_R);
    cudaGetSymbolAddress((void**)&z1,   g_z1);
    cudaGetSymbolAddress((void**)&w0p,  g_w0p);
    cudaGetSymbolAddress((void**)&w1c,  g_w1c);
    cudaGetSymbolAddress((void**)&w2c,  g_w2c);
    cudaGetSymbolAddress((void**)&wt1c, g_wt1c);

    static cudaStream_t s1 = nullptr;
    static cudaEvent_t evFork = nullptr, evJoin = nullptr;
    if (!s1) {
        cudaStreamCreateWithFlags(&s1, cudaStreamNonBlocking);
        cudaEventCreateWithFlags(&evFork, cudaEventDisableTiming);
        cudaEventCreateWithFlags(&evJoin, cudaEventDisableTiming);
    }

    dim3 blk(256);

    // fork: embedding gather + top-weight prep + out init on side stream
    cudaEventRecord(evFork, 0);
    cudaStreamWaitEvent(s1, evFork, 0);
    emb_pool_kernel<<<dim3(BATCH / 8, N_TABLES), blk, 0, s1>>>(lS_i, emb, feat);
    pad_w0_kernel<<<(512 * RLD + 255) / 256, blk, 0, s1>>>(tw0, w0p);
    cvt_copy_kernel<<<(256 * 512 + 255) / 256, blk, 0, s1>>>(tw1, wt1c, 256 * 512);
    out_init_kernel<<<(BATCH + 255) / 256, blk, 0, s1>>>(out, tb2);
    cudaEventRecord(evJoin, s1);

    // main stream: bottom-weight prep + bottom MLP chain
    cvt_copy_kernel<<<(256 * 512 + 255) / 256, blk>>>(bw1, w1c, 256 * 512);
    cvt_copy_kernel<<<(64 * 256 + 255) / 256, blk>>>(bw2, w2c, 64 * 256);
    bot0_kernel<<<BATCH / 32, blk>>>(dense_x, bw0, bb0, x1);
    gemm_tf32<<<dim3(256 / GTN, BATCH / GTM), blk>>>(x1, 512, w1c, 512, bb1, x2, 256, 512, 1);
    gemm_tf32_64<<<dim3(1, BATCH / 64), blk>>>(x2, 256, w2c, 256, bb2, feat, FEAT_LD, 256);

    // join
    cudaStreamWaitEvent(0, evJoin, 0);

    interact_mma<<<BATCH / 4, 128>>>(feat, R);

    // top MLP: 416(pad) -> 512 -> 256 -> 1 (final GEMV fused)
    gemm_tf32<<<dim3(512 / GTN, BATCH / GTM), blk>>>(R, RLD, w0p, RLD, tb0, z1, 512, RLD, 1);
    gemm_tf32_final<<<dim3(256 / GTN, BATCH / GTM), blk>>>(z1, 512, wt1c, 512, tb1, tw2, out, 512);
}